// round 4
// baseline (speedup 1.0000x reference)
#include <cuda_runtime.h>

#define NUM_CLASSES 1000
#define BATCH 8192
#define DD 4096
#define CE_BLOCKS 1024          // 8192 rows / 8 warps per block
#define DENSE_BLOCKS 4000       // 1000 classes * 4 column chunks

// ---- graph-safe scratch ----
__device__ double g_loss1;
__device__ double g_loss2;
__device__ int    g_offsets[NUM_CLASSES + 1];
__device__ int    g_sorted [BATCH];

__device__ __forceinline__ float tanh_fast(float x) {
    float y;
    asm("tanh.approx.f32 %0, %1;" : "=f"(y) : "f"(x));
    return y;
}

// ---------------------------------------------------------------------------
// K1: histogram + scan + counting-sort scatter, all in one block.
// Also writes total_accumulated and zeroes loss accumulators.
// ---------------------------------------------------------------------------
__global__ void prep_kernel(const int* __restrict__ target,
                            float* __restrict__ out_ta) {
    __shared__ int cnt[1024];
    __shared__ int s[1024];
    __shared__ int cur[1024];
    const int tid = threadIdx.x;
    cnt[tid] = 0;
    __syncthreads();
    int myt[8];
    #pragma unroll
    for (int k = 0; k < 8; ++k) {
        myt[k] = target[tid + k * 1024];
        atomicAdd(&cnt[myt[k]], 1);
    }
    __syncthreads();

    const int myc = (tid < NUM_CLASSES) ? cnt[tid] : 0;
    if (tid < NUM_CLASSES) out_ta[tid] = (float)myc;

    s[tid] = myc;
    __syncthreads();
    for (int off = 1; off < 1024; off <<= 1) {
        int t = (tid >= off) ? s[tid - off] : 0;
        __syncthreads();
        s[tid] += t;
        __syncthreads();
    }
    cur[tid] = s[tid] - myc;   // exclusive prefix
    if (tid < NUM_CLASSES) g_offsets[tid + 1] = s[tid];
    if (tid == 0) { g_offsets[0] = 0; g_loss1 = 0.0; g_loss2 = 0.0; }
    __syncthreads();

    // scatter: stable enough (order within class irrelevant — sums commute)
    #pragma unroll
    for (int k = 0; k < 8; ++k) {
        const int i = tid + k * 1024;
        const int p = atomicAdd(&cur[myt[k]], 1);
        g_sorted[p] = i;
    }
}

// ---------------------------------------------------------------------------
// K2: fused main kernel.
//   blockIdx.x <  CE_BLOCKS : cross-entropy (one warp per row, online softmax)
//   blockIdx.x >= CE_BLOCKS : dense segment-sum + BCE for one (class, chunk)
// ---------------------------------------------------------------------------
__device__ __forceinline__ void sig_bce(float x, float y, float& sig, float& bce) {
    const float t  = tanh_fast(0.5f * x);
    sig = fmaf(0.5f, t, 0.5f);                         // sigmoid(x)
    const float sp = fmaf(0.5f, fabsf(t), 0.5f);       // sigmoid(|x|)
    bce = fmaxf(x, 0.f) - x * y - __logf(sp);          // stable BCE w/ logits
}

__global__ __launch_bounds__(256) void main_kernel(
        const float* __restrict__ logits,
        const int*   __restrict__ target,
        const float* __restrict__ dense_out,
        const float* __restrict__ dense_labels,
        float* __restrict__ out_ds) {

    if (blockIdx.x < CE_BLOCKS) {
        // -------------------- cross-entropy --------------------
        const int warp = threadIdx.x >> 5;
        const int lane = threadIdx.x & 31;
        const int r    = blockIdx.x * 8 + warp;
        const float4* row = (const float4*)(logits + (size_t)r * NUM_CLASSES);

        float m = -1e30f, ssum = 0.f;
        #pragma unroll
        for (int k = 0; k < 8; ++k) {
            const int idx = k * 32 + lane;          // float4 index, 250 valid
            if (idx < NUM_CLASSES / 4) {
                const float4 v = row[idx];
                const float mv = fmaxf(fmaxf(v.x, v.y), fmaxf(v.z, v.w));
                const float mn = fmaxf(m, mv);
                ssum = ssum * __expf(m - mn)
                     + __expf(v.x - mn) + __expf(v.y - mn)
                     + __expf(v.z - mn) + __expf(v.w - mn);
                m = mn;
            }
        }
        #pragma unroll
        for (int off = 16; off; off >>= 1) {
            const float mo = __shfl_xor_sync(0xffffffffu, m, off);
            const float so = __shfl_xor_sync(0xffffffffu, ssum, off);
            const float mn = fmaxf(m, mo);
            ssum = ssum * __expf(m - mn) + so * __expf(mo - mn);
            m = mn;
        }

        __shared__ float part[8];
        if (lane == 0)
            part[warp] = (__logf(ssum) + m)
                       - logits[(size_t)r * NUM_CLASSES + target[r]];
        __syncthreads();
        if (threadIdx.x == 0) {
            float bs = 0.f;
            #pragma unroll
            for (int w = 0; w < 8; ++w) bs += part[w];
            atomicAdd(&g_loss1, (double)bs);
        }
    } else {
        // -------------------- dense segment-sum + BCE --------------------
        const int b    = blockIdx.x - CE_BLOCKS;
        const int c    = b >> 2;
        const int col4 = (b & 3) * 256 + threadIdx.x;     // float4 index 0..1023

        const float4 y = ((const float4*)(dense_labels + (size_t)c * DD))[col4];

        const int s = g_offsets[c];
        const int e = g_offsets[c + 1];

        float4 acc = make_float4(0.f, 0.f, 0.f, 0.f);
        float  lsum = 0.f;

        int i = s;
        for (; i + 2 <= e; i += 2) {                      // MLP=2 on row loads
            const int r0 = g_sorted[i];
            const int r1 = g_sorted[i + 1];
            const float4 x0 = ((const float4*)(dense_out + (size_t)r0 * DD))[col4];
            const float4 x1 = ((const float4*)(dense_out + (size_t)r1 * DD))[col4];
            float sg, bc;
            sig_bce(x0.x, y.x, sg, bc); acc.x += sg; lsum += bc;
            sig_bce(x0.y, y.y, sg, bc); acc.y += sg; lsum += bc;
            sig_bce(x0.z, y.z, sg, bc); acc.z += sg; lsum += bc;
            sig_bce(x0.w, y.w, sg, bc); acc.w += sg; lsum += bc;
            sig_bce(x1.x, y.x, sg, bc); acc.x += sg; lsum += bc;
            sig_bce(x1.y, y.y, sg, bc); acc.y += sg; lsum += bc;
            sig_bce(x1.z, y.z, sg, bc); acc.z += sg; lsum += bc;
            sig_bce(x1.w, y.w, sg, bc); acc.w += sg; lsum += bc;
        }
        if (i < e) {
            const int r0 = g_sorted[i];
            const float4 x0 = ((const float4*)(dense_out + (size_t)r0 * DD))[col4];
            float sg, bc;
            sig_bce(x0.x, y.x, sg, bc); acc.x += sg; lsum += bc;
            sig_bce(x0.y, y.y, sg, bc); acc.y += sg; lsum += bc;
            sig_bce(x0.z, y.z, sg, bc); acc.z += sg; lsum += bc;
            sig_bce(x0.w, y.w, sg, bc); acc.w += sg; lsum += bc;
        }

        float* dst = out_ds + (size_t)c * DD + (size_t)col4 * 4;  // 4B-aligned only
        dst[0] = acc.x; dst[1] = acc.y; dst[2] = acc.z; dst[3] = acc.w;

        #pragma unroll
        for (int o = 16; o; o >>= 1)
            lsum += __shfl_xor_sync(0xffffffffu, lsum, o);
        __shared__ float wpart[8];
        const int wid = threadIdx.x >> 5, lane = threadIdx.x & 31;
        if (lane == 0) wpart[wid] = lsum;
        __syncthreads();
        if (threadIdx.x == 0) {
            float bs = 0.f;
            #pragma unroll
            for (int w = 0; w < 8; ++w) bs += wpart[w];
            atomicAdd(&g_loss2, (double)bs);
        }
    }
}

// ---------------------------------------------------------------------------
__global__ void final_kernel(float* __restrict__ out) {
    const double l1 = g_loss1 / (double)BATCH;
    const double l2 = g_loss2 / ((double)BATCH * (double)DD);
    out[0] = (float)(0.5 * l1 + 0.5 * l2);
}

// ---------------------------------------------------------------------------
extern "C" void kernel_launch(void* const* d_in, const int* in_sizes, int n_in,
                              void* d_out, int out_size) {
    const float* logits       = (const float*)d_in[0];
    const float* dense_out    = (const float*)d_in[1];
    const int*   target       = (const int*)  d_in[2];
    const float* dense_labels = (const float*)d_in[3];

    float* out    = (float*)d_out;
    float* out_ds = out + 1;
    float* out_ta = out + 1 + (size_t)NUM_CLASSES * DD;

    prep_kernel<<<1, 1024>>>(target, out_ta);
    main_kernel<<<CE_BLOCKS + DENSE_BLOCKS, 256>>>(logits, target, dense_out,
                                                   dense_labels, out_ds);
    final_kernel<<<1, 1>>>(out);
}